// round 5
// baseline (speedup 1.0000x reference)
#include <cuda_runtime.h>
#include <cstdint>

// out[b,t,:] = tok_weight[x[b,t],:] + pos_weight[t,:]
// B=4, T=4096, E=512 fp32.
//
// One warp per (t, column-quarter). 16384 warps / 2048 CTAs -> ~14 CTAs/SM,
// ~90% occupancy, balanced waves. The 4 batch rows share pos_weight[t]
// (1 LDG.128, kept in a register). Gathers are split into two pairs with
// stores interleaved, capping front-batched LDG count (MLP_p1 ~ 7) to avoid
// cross-CTA L1tex-queue spread while SM-wide MLP stays high via warp count.

__global__ void __launch_bounds__(256) pos_embed_kernel(
    const int* __restrict__ x,            // [4*T]
    const float4* __restrict__ tok_w,     // [VOCAB, 128] float4
    const float4* __restrict__ pos_w,     // [T, 128] float4
    float4* __restrict__ out,             // [4*T, 128] float4
    int T)                                // 4096
{
    const int wid_global = blockIdx.x * (blockDim.x >> 5) + (threadIdx.x >> 5);
    const int t = wid_global >> 2;             // time step
    const int q = wid_global & 3;              // column quarter
    if (t >= T) return;
    const int lane = threadIdx.x & 31;
    const int col  = q * 32 + lane;            // float4 column (0..127)

    // Hoisted index loads (uniform per warp): one latency for all four.
    const int tok0 = __ldg(&x[t]);
    const int tok1 = __ldg(&x[t + T]);
    const int tok2 = __ldg(&x[t + 2 * T]);
    const int tok3 = __ldg(&x[t + 3 * T]);

    // pos quarter-row: 1 LDG.128 per lane, reused by all 4 batches
    const float4 p = __ldg(pos_w + (long long)t * 128 + col);

    const float4* __restrict__ g0 = tok_w + (long long)tok0 * 128 + col;
    const float4* __restrict__ g1 = tok_w + (long long)tok1 * 128 + col;
    const float4* __restrict__ g2 = tok_w + (long long)tok2 * 128 + col;
    const float4* __restrict__ g3 = tok_w + (long long)tok3 * 128 + col;
    float4* __restrict__ o0 = out + (long long)t * 128 + col;             // b=0
    float4* __restrict__ o1 = o0 + (long long)T * 128;                    // b=1
    float4* __restrict__ o2 = o1 + (long long)T * 128;                    // b=2
    float4* __restrict__ o3 = o2 + (long long)T * 128;                    // b=3

    // Pair 1: gather b0,b1 then store (bounded outstanding-load depth)
    float4 a = __ldg(g0);
    float4 b = __ldg(g1);
    float4 r;
    r.x = a.x + p.x; r.y = a.y + p.y; r.z = a.z + p.z; r.w = a.w + p.w; __stcs(o0, r);
    r.x = b.x + p.x; r.y = b.y + p.y; r.z = b.z + p.z; r.w = b.w + p.w; __stcs(o1, r);

    // Pair 2: gather b2,b3 then store
    float4 c = __ldg(g2);
    float4 d = __ldg(g3);
    r.x = c.x + p.x; r.y = c.y + p.y; r.z = c.z + p.z; r.w = c.w + p.w; __stcs(o2, r);
    r.x = d.x + p.x; r.y = d.y + p.y; r.z = d.z + p.z; r.w = d.w + p.w; __stcs(o3, r);
}

extern "C" void kernel_launch(void* const* d_in, const int* in_sizes, int n_in,
                              void* d_out, int out_size) {
    const int*    x     = (const int*)d_in[0];
    const float4* tok_w = (const float4*)d_in[1];
    const float4* pos_w = (const float4*)d_in[2];
    float4*       out   = (float4*)d_out;

    const int T = 4096;                       // fixed problem shape (B=4)
    const int total_warps = T * 4;            // (t, quarter) = 16384
    const int threads = 256;                  // 8 warps/block
    const int warps_per_blk = threads / 32;
    int blocks = (total_warps + warps_per_blk - 1) / warps_per_blk;  // 2048

    pos_embed_kernel<<<blocks, threads>>>(x, tok_w, pos_w, out, T);
}